// round 1
// baseline (speedup 1.0000x reference)
#include <cuda_runtime.h>

#define EPSF 1e-10f

static const int R   = 32;
static const int NB1 = 256;   // number of partial-Gram blocks

// Scratch (no allocations allowed): per-block partial Grams + final W
__device__ float2 g_scratch[NB1 * R * R];   // 2 MB
__device__ float2 g_W[R * R];

// ---------------------------------------------------------------------------
// K1: partial Gram. Block b accumulates G0[i][j] = sum_m conj(x[m,i])*x[m,j]
// over its row chunk. 256 threads = 8 warps; warp w owns i in [4w, 4w+4),
// lane j owns column j. Row data broadcast within the warp via shfl.
// ---------------------------------------------------------------------------
__global__ void gram_partial_kernel(const float2* __restrict__ x, int M) {
    const int b    = blockIdx.x;
    const int tid  = threadIdx.x;
    const int w    = tid >> 5;
    const int lane = tid & 31;
    const int ibase = w * 4;

    const int rows = (M + NB1 - 1) / NB1;
    const int m0 = b * rows;
    const int m1 = (m0 + rows < M) ? (m0 + rows) : M;

    float accre[4] = {0.f, 0.f, 0.f, 0.f};
    float accim[4] = {0.f, 0.f, 0.f, 0.f};

    for (int m = m0; m < m1; ++m) {
        float2 v = x[m * R + lane];           // x[m][lane]
        #pragma unroll
        for (int ii = 0; ii < 4; ++ii) {
            float ar = __shfl_sync(0xffffffffu, v.x, ibase + ii);  // x[m][i]
            float ai = __shfl_sync(0xffffffffu, v.y, ibase + ii);
            // conj(a) * v
            accre[ii] += ar * v.x + ai * v.y;
            accim[ii] += ar * v.y - ai * v.x;
        }
    }

    #pragma unroll
    for (int ii = 0; ii < 4; ++ii) {
        g_scratch[b * (R * R) + (ibase + ii) * R + lane] =
            make_float2(accre[ii], accim[ii]);
    }
}

// ---------------------------------------------------------------------------
// K2: single block, 1024 threads.
//   Phase A: deterministic reduce of NB1 partial Grams -> smem A (padded 33)
//   Phase B: in-place Cholesky of A = L L^H on warp 0 (no block barriers)
//   Phase C: back-substitution L^H w = e_j per warp j  ->  W = L^{-H}
// ---------------------------------------------------------------------------
__global__ void solve_kernel() {
    __shared__ float2 As[R * 33];   // padded stride 33 complex (2-way conflicts max)

    const int tid = threadIdx.x;

    // ---- Phase A: reduce partials (fixed order -> deterministic) ----
    {
        float2 s0 = make_float2(0.f, 0.f);
        float2 s1 = make_float2(0.f, 0.f);
        #pragma unroll 8
        for (int b = 0; b < NB1; b += 2) {
            float2 a = g_scratch[b * (R * R) + tid];
            float2 c = g_scratch[(b + 1) * (R * R) + tid];
            s0.x += a.x; s0.y += a.y;
            s1.x += c.x; s1.y += c.y;
        }
        const int i = tid >> 5, j = tid & 31;
        As[i * 33 + j] = make_float2(s0.x + s1.x, s0.y + s1.y);
    }
    __syncthreads();

    // ---- Phase B: Cholesky (warp 0 only, warp-synchronous) ----
    if (tid < 32) {
        const int lane = tid;
        for (int k = 0; k < R; ++k) {
            float akk = As[k * 33 + k].x;               // Schur-updated diag
            float d    = sqrtf(akk + EPSF);             // matches ref's +EPS in norm
            float invd = 1.0f / d;
            if (lane == 0) As[k * 33 + k] = make_float2(d, 0.f);

            float2 lpk = make_float2(0.f, 0.f);
            if (lane > k) {
                lpk = As[lane * 33 + k];
                lpk.x *= invd; lpk.y *= invd;
                As[lane * 33 + k] = lpk;                // L[p][k]
            }
            __syncwarp();

            // trailing update: A[p][q] -= L[p][k] * conj(L[q][k]),  p,q > k
            for (int q = k + 1; q < R; ++q) {
                float lqx = __shfl_sync(0xffffffffu, lpk.x, q);
                float lqy = __shfl_sync(0xffffffffu, lpk.y, q);
                if (lane > k) {
                    float2 a = As[lane * 33 + q];
                    a.x -= lpk.x * lqx + lpk.y * lqy;
                    a.y -= lpk.y * lqx - lpk.x * lqy;
                    As[lane * 33 + q] = a;
                }
            }
            __syncwarp();
        }
    }
    __syncthreads();

    // ---- Phase C: back-substitution, warp j solves L^H w = e_j ----
    {
        const int j    = tid >> 5;
        const int lane = tid & 31;
        const float invd = 1.0f / As[lane * 33 + lane].x;   // own diag (real)

        float2 acc = make_float2(0.f, 0.f);   // sum_{q'>p} conj(L[q'][p]) * w_q'
        float2 wp  = make_float2(0.f, 0.f);   // my w_p (stays 0 for p > j)

        for (int q = j; q >= 0; --q) {
            // candidate w for every lane; only lane q's is "real"
            float cre = (((lane == j) ? 1.f : 0.f) - acc.x) * invd;
            float cim = (-acc.y) * invd;
            float wr = __shfl_sync(0xffffffffu, cre, q);
            float wi = __shfl_sync(0xffffffffu, cim, q);
            if (lane == q) { wp.x = wr; wp.y = wi; }

            // acc_p += conj(L[q][p]) * w_q   for p < q
            float2 lqp = As[q * 33 + lane];   // conflict-free (consecutive lanes)
            if (lane < q) {
                acc.x += lqp.x * wr + lqp.y * wi;
                acc.y += lqp.x * wi - lqp.y * wr;
            }
        }
        g_W[lane * R + j] = wp;   // W[p][j], upper triangular
    }
}

// ---------------------------------------------------------------------------
// K3: Q = X * W.  One warp per row batch; lane j computes out[m][j].
// W column j is preloaded into registers; x[m][k] broadcast via shfl.
// ---------------------------------------------------------------------------
__global__ void apply_kernel(const float2* __restrict__ x,
                             float2* __restrict__ out, int M) {
    const int lane = threadIdx.x & 31;
    const int gw   = (blockIdx.x * blockDim.x + threadIdx.x) >> 5;
    const int GW   = (gridDim.x * blockDim.x) >> 5;

    // preload W[:, lane] into registers (32 coalesced loads, L2-resident)
    float wr[R], wi[R];
    #pragma unroll
    for (int k = 0; k < R; ++k) {
        float2 wv = g_W[k * R + lane];
        wr[k] = wv.x; wi[k] = wv.y;
    }

    const int rows = (M + GW - 1) / GW;
    const int m0 = gw * rows;
    const int m1 = (m0 + rows < M) ? (m0 + rows) : M;

    for (int m = m0; m < m1; ++m) {
        float2 v = x[m * R + lane];
        float or_ = 0.f, oi_ = 0.f;
        #pragma unroll
        for (int k = 0; k < R; ++k) {
            float ar = __shfl_sync(0xffffffffu, v.x, k);
            float ai = __shfl_sync(0xffffffffu, v.y, k);
            // (ar + i*ai) * (wr + i*wi)
            or_ += ar * wr[k] - ai * wi[k];
            oi_ += ar * wi[k] + ai * wr[k];
        }
        out[m * R + lane] = make_float2(or_, oi_);
    }
}

// ---------------------------------------------------------------------------
extern "C" void kernel_launch(void* const* d_in, const int* in_sizes, int n_in,
                              void* d_out, int out_size) {
    const float2* x  = (const float2*)d_in[0];
    float2* out      = (float2*)d_out;
    const int M = in_sizes[0] / (R * 2);   // 16384

    gram_partial_kernel<<<NB1, 256>>>(x, M);
    solve_kernel<<<1, 1024>>>();
    apply_kernel<<<256, 256>>>(x, out, M);
}

// round 2
// speedup vs baseline: 1.9053x; 1.9053x over previous
#include <cuda_runtime.h>

#define EPSF 1e-10f

static const int R   = 32;
static const int NB1 = 128;   // partial-Gram tiles

// Scratch (no allocations allowed): per-block partial Grams + final W
__device__ float2 g_scratch[NB1 * R * R];   // 1 MB
__device__ float2 g_W[R * R];

// ---------------------------------------------------------------------------
// K1: partial Gram, rows SPLIT across warps (no redundant loads).
// Block b owns rows [b*128, b*128+128); warp w owns 16 of them.
// Each warp computes a full 32x32 partial Gram in registers (lane = column j,
// acc[i] over i). Inner i-loop fully unrolled: 64 independent shfls + 128
// independent FFMAs per row -> issue-bound, latency hidden.
// Cross-warp reduce in smem (two stages, 32KB), one 8KB tile per block.
// ---------------------------------------------------------------------------
__global__ void gram_partial_kernel(const float2* __restrict__ x, int M) {
    const int b    = blockIdx.x;
    const int tid  = threadIdx.x;
    const int w    = tid >> 5;
    const int lane = tid & 31;

    const int rows_blk  = M / NB1;          // 128
    const int rows_warp = rows_blk / 8;     // 16
    const float2* xp = x + (size_t)(b * rows_blk + w * rows_warp) * R;

    float accre[R], accim[R];
    #pragma unroll
    for (int i = 0; i < R; ++i) { accre[i] = 0.f; accim[i] = 0.f; }

    for (int r = 0; r < rows_warp; ++r) {
        float2 v = xp[r * R + lane];
        #pragma unroll
        for (int i = 0; i < R; ++i) {
            float ar = __shfl_sync(0xffffffffu, v.x, i);
            float ai = __shfl_sync(0xffffffffu, v.y, i);
            accre[i] += ar * v.x + ai * v.y;   // conj(x_i) * x_j
            accim[i] += ar * v.y - ai * v.x;
        }
    }

    __shared__ float2 tiles[4][R * R];   // 32 KB

    if (w >= 4) {
        #pragma unroll
        for (int i = 0; i < R; ++i)
            tiles[w - 4][i * R + lane] = make_float2(accre[i], accim[i]);
    }
    __syncthreads();
    if (w < 4) {
        #pragma unroll
        for (int i = 0; i < R; ++i) {
            float2 t = tiles[w][i * R + lane];
            tiles[w][i * R + lane] = make_float2(accre[i] + t.x, accim[i] + t.y);
        }
    }
    __syncthreads();

    // final reduce 4 -> 1, coalesced global write of the 8KB tile
    for (int e = tid; e < R * R; e += 256) {
        float2 a = tiles[0][e], c = tiles[1][e], d = tiles[2][e], f = tiles[3][e];
        g_scratch[b * (R * R) + e] =
            make_float2(a.x + c.x + d.x + f.x, a.y + c.y + d.y + f.y);
    }
}

// ---------------------------------------------------------------------------
// K2: single block, 1024 threads.
//   Phase A: float4 reduce of NB1 partial tiles (1 MB, coalesced, high MLP)
//   Phase B: (p,q)-parallel Cholesky: thread (p,q) holds A[p][q] in a register;
//            per step: column broadcast via double-buffered smem, 1 barrier,
//            rank-1 Schur update = a few FMAs per thread.
//   Phase C: back-substitution L^H w = e_j, one warp per column j.
// ---------------------------------------------------------------------------
__global__ void solve_kernel() {
    __shared__ float2 As[R * 33];
    __shared__ float4 red[2][512];
    __shared__ float2 colbuf[2][R];

    const int tid = threadIdx.x;
    const int p = tid >> 5, q = tid & 31;

    // ---- Phase A ----
    {
        const int pairIdx = tid & 511;   // float4 index inside a tile
        const int half    = tid >> 9;    // tiles [0,64) or [64,128)
        const float4* src = (const float4*)g_scratch;
        float4 s = make_float4(0.f, 0.f, 0.f, 0.f);
        #pragma unroll 16
        for (int bb = 0; bb < NB1 / 2; ++bb) {
            int b = half * (NB1 / 2) + bb;
            float4 a = src[b * 512 + pairIdx];
            s.x += a.x; s.y += a.y; s.z += a.z; s.w += a.w;
        }
        red[half][pairIdx] = s;
    }
    __syncthreads();
    if (tid < 512) {
        float4 u = red[0][tid], v = red[1][tid];
        int e0 = tid * 2, e1 = e0 + 1;
        As[(e0 >> 5) * 33 + (e0 & 31)] = make_float2(u.x + v.x, u.y + v.y);
        As[(e1 >> 5) * 33 + (e1 & 31)] = make_float2(u.z + v.z, u.w + v.w);
    }
    __syncthreads();

    // ---- Phase B: parallel Cholesky ----
    float2 a = As[p * 33 + q];   // this thread's A[p][q]

    for (int k = 0; k < R; ++k) {
        if (q == k) colbuf[k & 1][p] = a;
        __syncthreads();
        float dkk = colbuf[k & 1][k].x;
        float rd  = rsqrtf(dkk + EPSF);
        float d   = (dkk + EPSF) * rd;          // sqrt(dkk+eps)
        float2 cp = colbuf[k & 1][p];
        float2 cq = colbuf[k & 1][q];
        float2 lp = make_float2(cp.x * rd, cp.y * rd);
        float2 lq = make_float2(cq.x * rd, cq.y * rd);
        if (p > k && q > k) {
            a.x -= lp.x * lq.x + lp.y * lq.y;   // A -= L[p][k] * conj(L[q][k])
            a.y -= lp.y * lq.x - lp.x * lq.y;
        }
        if (q == k) {
            if (p == k)      a = make_float2(d, 0.f);
            else if (p > k)  a = lp;            // finalized L[p][k]
        }
    }
    __syncthreads();
    As[p * 33 + q] = a;                          // L in lower triangle (+diag)
    __syncthreads();

    // ---- Phase C: warp j solves L^H w = e_j  ->  W = L^{-H} ----
    {
        const int j    = tid >> 5;
        const int lane = tid & 31;
        const float invd = 1.0f / As[lane * 33 + lane].x;

        float2 acc = make_float2(0.f, 0.f);
        float2 wp  = make_float2(0.f, 0.f);

        for (int qq = j; qq >= 0; --qq) {
            float cre = (((lane == j) ? 1.f : 0.f) - acc.x) * invd;
            float cim = (-acc.y) * invd;
            float wr = __shfl_sync(0xffffffffu, cre, qq);
            float wi = __shfl_sync(0xffffffffu, cim, qq);
            if (lane == qq) { wp.x = wr; wp.y = wi; }

            float2 lqp = As[qq * 33 + lane];     // L[qq][lane], conflict-free
            if (lane < qq) {
                acc.x += lqp.x * wr + lqp.y * wi;   // conj(L[qq][p]) * w_qq
                acc.y += lqp.x * wi - lqp.y * wr;
            }
        }
        g_W[lane * R + j] = wp;   // W[p][j]
    }
}

// ---------------------------------------------------------------------------
// K3: Q = X * W.  1024 warps, 16 rows each; lane j computes out[m][j].
// W column j register-resident; x[m][k] broadcast via shfl; k-loop unrolled.
// ---------------------------------------------------------------------------
__global__ void apply_kernel(const float2* __restrict__ x,
                             float2* __restrict__ out, int M) {
    const int lane = threadIdx.x & 31;
    const int gw   = (blockIdx.x * blockDim.x + threadIdx.x) >> 5;
    const int GW   = (gridDim.x * blockDim.x) >> 5;

    float wr[R], wi[R];
    #pragma unroll
    for (int k = 0; k < R; ++k) {
        float2 wv = g_W[k * R + lane];
        wr[k] = wv.x; wi[k] = wv.y;
    }

    const int rows = M / GW;          // 16
    const int m0 = gw * rows;

    #pragma unroll 2
    for (int r = 0; r < rows; ++r) {
        int m = m0 + r;
        float2 v = x[m * R + lane];
        float or_ = 0.f, oi_ = 0.f;
        #pragma unroll
        for (int k = 0; k < R; ++k) {
            float ar = __shfl_sync(0xffffffffu, v.x, k);
            float ai = __shfl_sync(0xffffffffu, v.y, k);
            or_ += ar * wr[k] - ai * wi[k];
            oi_ += ar * wi[k] + ai * wr[k];
        }
        out[m * R + lane] = make_float2(or_, oi_);
    }
}

// ---------------------------------------------------------------------------
extern "C" void kernel_launch(void* const* d_in, const int* in_sizes, int n_in,
                              void* d_out, int out_size) {
    const float2* x  = (const float2*)d_in[0];
    float2* out      = (float2*)d_out;
    const int M = in_sizes[0] / (R * 2);   // 16384

    gram_partial_kernel<<<NB1, 256>>>(x, M);
    solve_kernel<<<1, 1024>>>();
    apply_kernel<<<128, 256>>>(x, out, M);
}